// round 1
// baseline (speedup 1.0000x reference)
#include <cuda_runtime.h>
#include <cstdint>
#include <math.h>

// ---------------------------------------------------------------------------
// Problem constants
// ---------------------------------------------------------------------------
#define S_LEN   2048
#define BATCH   4
#define DIM_    1024
#define D_INNER 2048
#define D_ST    16
#define M_ROWS  (BATCH * S_LEN)      // 8192
#define NCHUNK  16
#define LCHUNK  (S_LEN / NCHUNK)     // 128

typedef unsigned long long ull;

// ---------------------------------------------------------------------------
// Scratch (static __device__ — no allocations allowed in kernel_launch)
// ---------------------------------------------------------------------------
__device__ float g_xr [(size_t)M_ROWS * 4096];              // [m][0:2048)=x_copy, [2048:4096)=res
__device__ float g_y  [(size_t)M_ROWS * D_INNER];           // gated scan output (GEMM2 input)
__device__ float g_dA [M_ROWS * D_ST];                      // exp(-delta*sp(A))
__device__ float g_gs [M_ROWS];                             // silu(gamma)
__device__ float g_Ap [BATCH * NCHUNK * D_ST];              // per-chunk prod of dA
__device__ float g_hend[(size_t)BATCH * NCHUNK * D_INNER * D_ST];
__device__ float g_hin [(size_t)BATCH * NCHUNK * D_INNER * D_ST];

// ---------------------------------------------------------------------------
// Helpers
// ---------------------------------------------------------------------------
__device__ __forceinline__ float sp_(float x) {            // softplus
    return x > 20.f ? x : log1pf(expf(x));
}

__device__ __forceinline__ ull pack2(float lo, float hi) {
    ull r; asm("mov.b64 %0, {%1, %2};" : "=l"(r) : "f"(lo), "f"(hi)); return r;
}
__device__ __forceinline__ ull fma2(ull a, ull b, ull c) { // packed f32x2 FMA (Blackwell)
    ull d; asm("fma.rn.f32x2 %0, %1, %2, %3;" : "=l"(d) : "l"(a), "l"(b), "l"(c)); return d;
}
__device__ __forceinline__ float2 unpack2(ull v) {
    float lo, hi; asm("mov.b64 {%0, %1}, %2;" : "=f"(lo), "=f"(hi) : "l"(v));
    return make_float2(lo, hi);
}

// ---------------------------------------------------------------------------
// GEMM:  C[M,N] = A[M,K] @ W[N,K]^T + bias[N]      (all row-major fp32)
// 128x128 tile, BK=16, 256 threads, 8x8 per thread, f32x2 accumulators.
// M,N multiples of 128; K multiple of 16 (true for both call sites).
// ---------------------------------------------------------------------------
#define BM 128
#define BN 128
#define BKK 16

__global__ __launch_bounds__(256, 2)
void gemm_abt(const float* __restrict__ A, const float* __restrict__ W,
              const float* __restrict__ bias, float* __restrict__ C,
              int M, int N, int K)
{
    __shared__ float As[BKK][BM];
    __shared__ float Bs[BKK][BN];
    const int tid = threadIdx.x;
    const int tx = tid & 15, ty = tid >> 4;

    const size_t aBase = (size_t)blockIdx.y * BM * K;
    const size_t bBase = (size_t)blockIdx.x * BN * K;

    ull acc[8][4];
#pragma unroll
    for (int i = 0; i < 8; i++)
#pragma unroll
        for (int j = 0; j < 4; j++) acc[i][j] = 0ull;      // {+0.f,+0.f}

    const int r0 = tid >> 2;          // 0..63
    const int c0 = (tid & 3) * 4;     // 0,4,8,12

    for (int k0 = 0; k0 < K; k0 += BKK) {
#pragma unroll
        for (int h = 0; h < 2; h++) {
            const int row = r0 + h * 64;
            float4 va = *(const float4*)(A + aBase + (size_t)row * K + k0 + c0);
            As[c0 + 0][row] = va.x; As[c0 + 1][row] = va.y;
            As[c0 + 2][row] = va.z; As[c0 + 3][row] = va.w;
            float4 vb = *(const float4*)(W + bBase + (size_t)row * K + k0 + c0);
            Bs[c0 + 0][row] = vb.x; Bs[c0 + 1][row] = vb.y;
            Bs[c0 + 2][row] = vb.z; Bs[c0 + 3][row] = vb.w;
        }
        __syncthreads();
#pragma unroll
        for (int k = 0; k < BKK; k++) {
            float4 a0 = *(const float4*)&As[k][ty * 8];
            float4 a1 = *(const float4*)&As[k][ty * 8 + 4];
            const ull* bp = (const ull*)&Bs[k][tx * 8];
            ull b0 = bp[0], b1 = bp[1], b2 = bp[2], b3 = bp[3];
            float av[8] = {a0.x, a0.y, a0.z, a0.w, a1.x, a1.y, a1.z, a1.w};
#pragma unroll
            for (int i = 0; i < 8; i++) {
                ull ap = pack2(av[i], av[i]);
                acc[i][0] = fma2(ap, b0, acc[i][0]);
                acc[i][1] = fma2(ap, b1, acc[i][1]);
                acc[i][2] = fma2(ap, b2, acc[i][2]);
                acc[i][3] = fma2(ap, b3, acc[i][3]);
            }
        }
        __syncthreads();
    }

    const int cn = blockIdx.x * BN + tx * 8;
    const int cm = blockIdx.y * BM + ty * 8;
    float bv[8];
#pragma unroll
    for (int j = 0; j < 8; j++) bv[j] = bias[cn + j];
#pragma unroll
    for (int i = 0; i < 8; i++) {
        float o[8];
#pragma unroll
        for (int j = 0; j < 4; j++) {
            float2 p = unpack2(acc[i][j]);
            o[2 * j]     = p.x + bv[2 * j];
            o[2 * j + 1] = p.y + bv[2 * j + 1];
        }
        *(float4*)(C + (size_t)(cm + i) * N + cn)     = make_float4(o[0], o[1], o[2], o[3]);
        *(float4*)(C + (size_t)(cm + i) * N + cn + 4) = make_float4(o[4], o[5], o[6], o[7]);
    }
}

// ---------------------------------------------------------------------------
// Fused conv(depthwise,4) + gamma/delta projections -> dA, silu(gamma)
// One block per token (b,t). 256 threads x 8 channels each. conv_state never
// materialized. 17 block reductions (16 delta channels + gamma).
// ---------------------------------------------------------------------------
__global__ __launch_bounds__(256)
void conv_proj(const float* __restrict__ conv_w, const float* __restrict__ conv_b,
               const float* __restrict__ xproj_w, const float* __restrict__ xproj_b,
               const float* __restrict__ dt_w, const float* __restrict__ dt_b,
               const float* __restrict__ Avec)
{
    const int m = blockIdx.x;
    const int b = m >> 11, t = m & (S_LEN - 1);
    const int tid = threadIdx.x, lane = tid & 31, wid = tid >> 5;
    const float* xc = g_xr + (size_t)b * S_LEN * 4096;   // x_copy rows, stride 4096
    const float* w20 = xproj_w + 20 * D_INNER;

    float part[17];
#pragma unroll
    for (int r = 0; r < 17; r++) part[r] = 0.f;

#pragma unroll
    for (int g = 0; g < 2; g++) {
        const int d = (tid << 3) + (g << 2);
        float wmat[4][4];
#pragma unroll
        for (int q = 0; q < 4; q++) {
            float4 cwv = *(const float4*)(conv_w + (d + q) * 4);
            wmat[q][0] = cwv.x; wmat[q][1] = cwv.y; wmat[q][2] = cwv.z; wmat[q][3] = cwv.w;
        }
        float4 cbv = *(const float4*)(conv_b + d);
        float cs[4] = {cbv.x, cbv.y, cbv.z, cbv.w};
#pragma unroll
        for (int k = 0; k < 4; k++) {
            const int tk = t - 1 + k;
            if (tk >= 0 && tk < S_LEN) {
                float4 xv = *(const float4*)(xc + (size_t)tk * 4096 + d);
                cs[0] = fmaf(wmat[0][k], xv.x, cs[0]);
                cs[1] = fmaf(wmat[1][k], xv.y, cs[1]);
                cs[2] = fmaf(wmat[2][k], xv.z, cs[2]);
                cs[3] = fmaf(wmat[3][k], xv.w, cs[3]);
            }
        }
        float4 wg = *(const float4*)(w20 + d);
        part[16] += cs[0]*wg.x + cs[1]*wg.y + cs[2]*wg.z + cs[3]*wg.w;
#pragma unroll
        for (int n = 0; n < 16; n++) {
            float4 wv = *(const float4*)(dt_w + n * D_INNER + d);
            part[n] = fmaf(cs[0], wv.x, fmaf(cs[1], wv.y,
                      fmaf(cs[2], wv.z, fmaf(cs[3], wv.w, part[n]))));
        }
    }

    __shared__ float red[8][17];
#pragma unroll
    for (int r = 0; r < 17; r++) {
        float v = part[r];
#pragma unroll
        for (int o = 16; o > 0; o >>= 1) v += __shfl_down_sync(0xffffffffu, v, o);
        if (lane == 0) red[wid][r] = v;
    }
    __syncthreads();
    if (tid < 16) {
        float s = 0.f;
#pragma unroll
        for (int w = 0; w < 8; w++) s += red[w][tid];
        const float delta = sp_(s + dt_b[tid]);
        const float spA   = sp_(Avec[tid]);
        g_dA[m * D_ST + tid] = expf(-delta * spA);
    } else if (tid == 16) {
        float s = 0.f;
#pragma unroll
        for (int w = 0; w < 8; w++) s += red[w][16];
        const float gamma = s + xproj_b[20];
        g_gs[m] = gamma / (1.f + expf(-gamma));
    }
}

// ---------------------------------------------------------------------------
// Per-chunk products of dA  (carry transition matrices; d-independent)
// ---------------------------------------------------------------------------
__global__ void aprod_kernel()
{
    const int bc = blockIdx.x;            // (b,c)
    const int n = threadIdx.x;
    const int b = bc / NCHUNK, c = bc % NCHUNK;
    float p = 1.f;
    const int base = (b * S_LEN + c * LCHUNK) * D_ST + n;
    for (int i = 0; i < LCHUNK; i++) p *= g_dA[base + i * D_ST];
    g_Ap[bc * D_ST + n] = p;
}

// ---------------------------------------------------------------------------
// Scan pass 1: local chunk scan (h starts at 0) -> h_end per (b,c,d)
// ---------------------------------------------------------------------------
__global__ __launch_bounds__(256)
void scan_pass1(const float* __restrict__ Bm)
{
    const int gid = blockIdx.x;                 // b*128 + c*8 + dblk
    const int d = ((gid & 7) << 8) + threadIdx.x;
    const int c = (gid >> 3) & (NCHUNK - 1);
    const int b = gid >> 7;

    float dB[16];
#pragma unroll
    for (int q = 0; q < 4; q++) {
        float4 v = *(const float4*)(Bm + d * D_ST + 4 * q);
        dB[4*q+0] = sp_(v.x); dB[4*q+1] = sp_(v.y); dB[4*q+2] = sp_(v.z); dB[4*q+3] = sp_(v.w);
    }
    float h[16];
#pragma unroll
    for (int n = 0; n < 16; n++) h[n] = 0.f;

    const int m0 = b * S_LEN + c * LCHUNK;
    const float* xp = g_xr + (size_t)m0 * 4096 + d;
    const float* ap = g_dA + (size_t)m0 * D_ST;

    for (int i = 0; i < LCHUNK; i++) {
        const float u = __ldg(xp + (size_t)i * 4096);
#pragma unroll
        for (int q = 0; q < 4; q++) {
            float4 a4 = *(const float4*)(ap + i * D_ST + 4 * q);
            h[4*q+0] = fmaf(h[4*q+0], a4.x, u * dB[4*q+0]);
            h[4*q+1] = fmaf(h[4*q+1], a4.y, u * dB[4*q+1]);
            h[4*q+2] = fmaf(h[4*q+2], a4.z, u * dB[4*q+2]);
            h[4*q+3] = fmaf(h[4*q+3], a4.w, u * dB[4*q+3]);
        }
    }
    const size_t o = ((size_t)(b * NCHUNK + c) * D_INNER + d) * D_ST;
#pragma unroll
    for (int q = 0; q < 4; q++)
        *(float4*)(g_hend + o + 4 * q) = make_float4(h[4*q], h[4*q+1], h[4*q+2], h[4*q+3]);
}

// ---------------------------------------------------------------------------
// Inter-chunk carry: h_in(c) = Aprod(c-1)*h_in(c-1) + h_end(c-1)
// one thread per (b,d,n)
// ---------------------------------------------------------------------------
__global__ void scan_carry()
{
    const int lin = blockIdx.x * 256 + threadIdx.x;   // (b,d,n)
    const int n = lin & 15;
    const int d = (lin >> 4) & (D_INNER - 1);
    const int b = lin >> 15;
    float h = 0.f;
    for (int c = 0; c < NCHUNK; c++) {
        const size_t idx = ((size_t)(b * NCHUNK + c) * D_INNER + d) * D_ST + n;
        g_hin[idx] = h;
        h = h * g_Ap[(b * NCHUNK + c) * D_ST + n] + g_hend[idx];
    }
}

// ---------------------------------------------------------------------------
// Scan pass 2: re-scan with carried h_in, produce y*silu(gamma)+res -> g_y
// ---------------------------------------------------------------------------
__global__ __launch_bounds__(256)
void scan_pass2(const float* __restrict__ Bm, const float* __restrict__ Cm)
{
    const int gid = blockIdx.x;
    const int d = ((gid & 7) << 8) + threadIdx.x;
    const int c = (gid >> 3) & (NCHUNK - 1);
    const int b = gid >> 7;

    float dB[16], dC[16];
#pragma unroll
    for (int q = 0; q < 4; q++) {
        float4 v = *(const float4*)(Bm + d * D_ST + 4 * q);
        dB[4*q+0] = sp_(v.x); dB[4*q+1] = sp_(v.y); dB[4*q+2] = sp_(v.z); dB[4*q+3] = sp_(v.w);
        float4 w = *(const float4*)(Cm + d * D_ST + 4 * q);
        dC[4*q+0] = w.x; dC[4*q+1] = w.y; dC[4*q+2] = w.z; dC[4*q+3] = w.w;
    }
    const size_t o = ((size_t)(b * NCHUNK + c) * D_INNER + d) * D_ST;
    float h[16];
#pragma unroll
    for (int q = 0; q < 4; q++) {
        float4 v = *(const float4*)(g_hin + o + 4 * q);
        h[4*q+0] = v.x; h[4*q+1] = v.y; h[4*q+2] = v.z; h[4*q+3] = v.w;
    }

    const int m0 = b * S_LEN + c * LCHUNK;
    const float* xp = g_xr + (size_t)m0 * 4096 + d;          // x_copy
    const float* rp = g_xr + (size_t)m0 * 4096 + D_INNER + d; // res
    const float* ap = g_dA + (size_t)m0 * D_ST;
    float* yp = g_y + (size_t)m0 * D_INNER + d;

    for (int i = 0; i < LCHUNK; i++) {
        const float u = __ldg(xp + (size_t)i * 4096);
        float y = 0.f;
#pragma unroll
        for (int q = 0; q < 4; q++) {
            float4 a4 = *(const float4*)(ap + i * D_ST + 4 * q);
            h[4*q+0] = fmaf(h[4*q+0], a4.x, u * dB[4*q+0]);
            h[4*q+1] = fmaf(h[4*q+1], a4.y, u * dB[4*q+1]);
            h[4*q+2] = fmaf(h[4*q+2], a4.z, u * dB[4*q+2]);
            h[4*q+3] = fmaf(h[4*q+3], a4.w, u * dB[4*q+3]);
            y = fmaf(h[4*q+0], dC[4*q+0], y);
            y = fmaf(h[4*q+1], dC[4*q+1], y);
            y = fmaf(h[4*q+2], dC[4*q+2], y);
            y = fmaf(h[4*q+3], dC[4*q+3], y);
        }
        const float gs = g_gs[m0 + i];
        yp[(size_t)i * D_INNER] = fmaf(y, gs, __ldg(rp + (size_t)i * 4096));
    }
}

// ---------------------------------------------------------------------------
// Launch
// ---------------------------------------------------------------------------
extern "C" void kernel_launch(void* const* d_in, const int* in_sizes, int n_in,
                              void* d_out, int out_size)
{
    const float* x       = (const float*)d_in[0];
    const float* in_w    = (const float*)d_in[1];
    const float* in_b    = (const float*)d_in[2];
    const float* conv_w  = (const float*)d_in[3];
    const float* conv_b  = (const float*)d_in[4];
    const float* xproj_w = (const float*)d_in[5];
    const float* xproj_b = (const float*)d_in[6];
    const float* dt_w    = (const float*)d_in[7];
    const float* dt_b    = (const float*)d_in[8];
    const float* A       = (const float*)d_in[9];
    const float* Bm      = (const float*)d_in[10];
    const float* Cm      = (const float*)d_in[11];
    const float* out_w   = (const float*)d_in[12];
    const float* out_b   = (const float*)d_in[13];
    float* out = (float*)d_out;

    float *xr = nullptr, *y = nullptr;
    cudaGetSymbolAddress((void**)&xr, g_xr);
    cudaGetSymbolAddress((void**)&y,  g_y);

    // GEMM1: x_and_res = x @ in_w^T + in_b   -> g_xr [8192, 4096]
    gemm_abt<<<dim3(4096 / BN, M_ROWS / BM), 256>>>(x, in_w, in_b, xr,
                                                    M_ROWS, 4096, DIM_);
    // conv + gamma/delta projections -> g_dA, g_gs
    conv_proj<<<M_ROWS, 256>>>(conv_w, conv_b, xproj_w, xproj_b, dt_w, dt_b, A);
    // chunked scan
    aprod_kernel<<<BATCH * NCHUNK, D_ST>>>();
    scan_pass1<<<BATCH * NCHUNK * (D_INNER / 256), 256>>>(Bm);
    scan_carry<<<(BATCH * D_INNER * D_ST) / 256, 256>>>();
    scan_pass2<<<BATCH * NCHUNK * (D_INNER / 256), 256>>>(Bm, Cm);
    // GEMM2: out = g_y @ out_w^T + out_b
    gemm_abt<<<dim3(1024 / BN, M_ROWS / BM), 256>>>(y, out_w, out_b, out,
                                                    M_ROWS, 1024, D_INNER);
}

// round 4
// speedup vs baseline: 2.7716x; 2.7716x over previous
#include <cuda_runtime.h>
#include <cstdint>
#include <math.h>

// ---------------------------------------------------------------------------
// Problem constants
// ---------------------------------------------------------------------------
#define S_LEN   2048
#define BATCH   4
#define DIM_    1024
#define D_INNER 2048
#define D_ST    16
#define M_ROWS  (BATCH * S_LEN)      // 8192
#define NCHUNK  16
#define LCHUNK  (S_LEN / NCHUNK)     // 128

// ---------------------------------------------------------------------------
// Scratch (static __device__ — no allocations allowed)
// ---------------------------------------------------------------------------
__device__ float g_xr [(size_t)M_ROWS * 4096];              // [m][0:2048)=x_copy, [2048:4096)=res
__device__ float g_y  [(size_t)M_ROWS * D_INNER];           // gated scan output (tf32-rounded)
__device__ float g_dA [M_ROWS * D_ST];
__device__ float g_gs [M_ROWS];
__device__ float g_Ap [BATCH * NCHUNK * D_ST];
__device__ float g_hend[(size_t)BATCH * NCHUNK * D_INNER * D_ST];
__device__ float g_hin [(size_t)BATCH * NCHUNK * D_INNER * D_ST];
__device__ float g_xt [(size_t)M_ROWS * DIM_];              // tf32-rounded x
__device__ float g_w1t[(size_t)4096 * DIM_];                // tf32-rounded in_w
__device__ float g_w2t[(size_t)DIM_ * D_INNER];             // tf32-rounded out_w

// ---------------------------------------------------------------------------
// Helpers
// ---------------------------------------------------------------------------
__device__ __forceinline__ float sp_(float x) { return x > 20.f ? x : log1pf(expf(x)); }

__device__ __forceinline__ float tf32r(float x) {
    // NB: cvt.*.tf32.f32 requires a .b32 destination register
    uint32_t r; asm("cvt.rna.tf32.f32 %0, %1;" : "=r"(r) : "f"(x));
    return __uint_as_float(r);
}
__device__ __forceinline__ uint32_t s2u(const void* p) {
    uint32_t a;
    asm("{ .reg .u64 t; cvta.to.shared.u64 t, %1; cvt.u32.u64 %0, t; }" : "=r"(a) : "l"(p));
    return a;
}
__device__ __forceinline__ void cpa16(uint32_t dst, const float* src) {
    asm volatile("cp.async.cg.shared.global [%0], [%1], 16;" :: "r"(dst), "l"(src) : "memory");
}
__device__ __forceinline__ void mma8(float* d, const uint32_t* a, const uint32_t* b) {
    asm volatile("mma.sync.aligned.m16n8k8.row.col.f32.tf32.tf32.f32 "
        "{%0,%1,%2,%3}, {%4,%5,%6,%7}, {%8,%9}, {%0,%1,%2,%3};"
        : "+f"(d[0]), "+f"(d[1]), "+f"(d[2]), "+f"(d[3])
        : "r"(a[0]), "r"(a[1]), "r"(a[2]), "r"(a[3]), "r"(b[0]), "r"(b[1]));
}

// ---------------------------------------------------------------------------
// tf32 round-to-nearest conversion (float4 grid-stride)
// ---------------------------------------------------------------------------
__global__ void k_tf32round(const float4* __restrict__ in, float4* __restrict__ out, int n4)
{
    for (int i = blockIdx.x * blockDim.x + threadIdx.x; i < n4; i += gridDim.x * blockDim.x) {
        float4 v = in[i];
        v.x = tf32r(v.x); v.y = tf32r(v.y); v.z = tf32r(v.z); v.w = tf32r(v.w);
        out[i] = v;
    }
}

// ---------------------------------------------------------------------------
// TF32 mma.sync GEMM:  C[M,NN] = A[M,K] @ W[NN,K]^T + bias
//  - 128x128 CTA tile, K-tile 32, 3-stage cp.async pipeline
//  - 8 warps (4m x 2n), 32x64 warp tile, m16n8k8 tf32 MMA
//  - smem rows padded to 36 floats (144B): conflict-free LDS + aligned cp.async
// ---------------------------------------------------------------------------
#define ROWPAD 36
#define STG_F  (128 * ROWPAD)                 // floats per tile-stage
#define GSMEM_BYTES (2 * 3 * STG_F * 4)       // 110592

template<int KDIM, int NN>
__global__ __launch_bounds__(256, 2)
void gemm_mma(const float* __restrict__ A, const float* __restrict__ W,
              const float* __restrict__ bias, float* __restrict__ C)
{
    constexpr int T = KDIM / 32;
    extern __shared__ __align__(16) float smem[];
    float* As = smem;                 // [3][128][36]
    float* Bs = smem + 3 * STG_F;     // [3][128][36]
    const uint32_t asu = s2u(As), bsu = s2u(Bs);

    const int tid  = threadIdx.x;
    const int lane = tid & 31, warp = tid >> 5;
    const int warpM = warp & 3, warpN = warp >> 2;
    const int gID = lane >> 2, tig = lane & 3;
    const int mBase = blockIdx.y * 128, nBase = blockIdx.x * 128;

    float acc[2][8][4];
#pragma unroll
    for (int i = 0; i < 2; i++)
#pragma unroll
        for (int j = 0; j < 8; j++)
#pragma unroll
            for (int q = 0; q < 4; q++) acc[i][j][q] = 0.f;

    // ---- async tile loader ----
    auto load_stage = [&](int t, int s) {
        const int k0 = t * 32;
#pragma unroll
        for (int i = 0; i < 4; i++) {
            const int c = i * 256 + tid;        // 0..1023
            const int row = c >> 3, c16 = c & 7;
            const uint32_t so = (uint32_t)(s * STG_F + row * ROWPAD + c16 * 4) * 4u;
            cpa16(asu + so, A + (size_t)(mBase + row) * KDIM + k0 + c16 * 4);
            cpa16(bsu + so, W + (size_t)(nBase + row) * KDIM + k0 + c16 * 4);
        }
        asm volatile("cp.async.commit_group;" ::: "memory");
    };

    load_stage(0, 0);
    if (T > 1) load_stage(1, 1);

    for (int t = 0; t < T; t++) {
        const int s = t - (t / 3) * 3;
        if (t + 2 < T) { asm volatile("cp.async.wait_group 1;" ::: "memory"); }
        else           { asm volatile("cp.async.wait_group 0;" ::: "memory"); }
        __syncthreads();
        if (t + 2 < T) load_stage(t + 2, (t + 2) - ((t + 2) / 3) * 3);

        const float* arow = As + s * STG_F + (warpM * 32 + gID) * ROWPAD;
        const float* brow = Bs + s * STG_F + (warpN * 64 + gID) * ROWPAD;
#pragma unroll
        for (int kk = 0; kk < 4; kk++) {
            const int k0 = kk * 8;
            uint32_t a[2][4], b[8][2];
#pragma unroll
            for (int i = 0; i < 2; i++) {
                const float* ap = arow + i * 16 * ROWPAD;
                a[i][0] = __float_as_uint(ap[k0 + tig]);
                a[i][1] = __float_as_uint(ap[8 * ROWPAD + k0 + tig]);
                a[i][2] = __float_as_uint(ap[k0 + tig + 4]);
                a[i][3] = __float_as_uint(ap[8 * ROWPAD + k0 + tig + 4]);
            }
#pragma unroll
            for (int j = 0; j < 8; j++) {
                const float* bp = brow + j * 8 * ROWPAD;
                b[j][0] = __float_as_uint(bp[k0 + tig]);
                b[j][1] = __float_as_uint(bp[k0 + tig + 4]);
            }
#pragma unroll
            for (int i = 0; i < 2; i++)
#pragma unroll
                for (int j = 0; j < 8; j++)
                    mma8(acc[i][j], a[i], b[j]);
        }
    }

    // ---- epilogue ----
    const int row0 = mBase + warpM * 32 + gID;
    const int col0 = nBase + warpN * 64 + tig * 2;
#pragma unroll
    for (int i = 0; i < 2; i++) {
#pragma unroll
        for (int j = 0; j < 8; j++) {
            const int r = row0 + i * 16;
            const int cc = col0 + j * 8;
            const float b0 = __ldg(bias + cc), b1 = __ldg(bias + cc + 1);
            *(float2*)(C + (size_t)r * NN + cc) =
                make_float2(acc[i][j][0] + b0, acc[i][j][1] + b1);
            *(float2*)(C + (size_t)(r + 8) * NN + cc) =
                make_float2(acc[i][j][2] + b0, acc[i][j][3] + b1);
        }
    }
}

// ---------------------------------------------------------------------------
// Fused conv(depthwise,4) + gamma/delta projections -> dA, silu(gamma)
// ---------------------------------------------------------------------------
__global__ __launch_bounds__(256)
void conv_proj(const float* __restrict__ conv_w, const float* __restrict__ conv_b,
               const float* __restrict__ xproj_w, const float* __restrict__ xproj_b,
               const float* __restrict__ dt_w, const float* __restrict__ dt_b,
               const float* __restrict__ Avec)
{
    const int m = blockIdx.x;
    const int b = m >> 11, t = m & (S_LEN - 1);
    const int tid = threadIdx.x, lane = tid & 31, wid = tid >> 5;
    const float* xc = g_xr + (size_t)b * S_LEN * 4096;
    const float* w20 = xproj_w + 20 * D_INNER;

    float part[17];
#pragma unroll
    for (int r = 0; r < 17; r++) part[r] = 0.f;

#pragma unroll
    for (int g = 0; g < 2; g++) {
        const int d = (tid << 3) + (g << 2);
        float wmat[4][4];
#pragma unroll
        for (int q = 0; q < 4; q++) {
            float4 cwv = *(const float4*)(conv_w + (d + q) * 4);
            wmat[q][0] = cwv.x; wmat[q][1] = cwv.y; wmat[q][2] = cwv.z; wmat[q][3] = cwv.w;
        }
        float4 cbv = *(const float4*)(conv_b + d);
        float cs[4] = {cbv.x, cbv.y, cbv.z, cbv.w};
#pragma unroll
        for (int k = 0; k < 4; k++) {
            const int tk = t - 1 + k;
            if (tk >= 0 && tk < S_LEN) {
                float4 xv = *(const float4*)(xc + (size_t)tk * 4096 + d);
                cs[0] = fmaf(wmat[0][k], xv.x, cs[0]);
                cs[1] = fmaf(wmat[1][k], xv.y, cs[1]);
                cs[2] = fmaf(wmat[2][k], xv.z, cs[2]);
                cs[3] = fmaf(wmat[3][k], xv.w, cs[3]);
            }
        }
        float4 wg = *(const float4*)(w20 + d);
        part[16] += cs[0]*wg.x + cs[1]*wg.y + cs[2]*wg.z + cs[3]*wg.w;
#pragma unroll
        for (int n = 0; n < 16; n++) {
            float4 wv = *(const float4*)(dt_w + n * D_INNER + d);
            part[n] = fmaf(cs[0], wv.x, fmaf(cs[1], wv.y,
                      fmaf(cs[2], wv.z, fmaf(cs[3], wv.w, part[n]))));
        }
    }

    __shared__ float red[8][17];
#pragma unroll
    for (int r = 0; r < 17; r++) {
        float v = part[r];
#pragma unroll
        for (int o = 16; o > 0; o >>= 1) v += __shfl_down_sync(0xffffffffu, v, o);
        if (lane == 0) red[wid][r] = v;
    }
    __syncthreads();
    if (tid < 16) {
        float s = 0.f;
#pragma unroll
        for (int w = 0; w < 8; w++) s += red[w][tid];
        const float delta = sp_(s + dt_b[tid]);
        const float spA   = sp_(Avec[tid]);
        g_dA[m * D_ST + tid] = expf(-delta * spA);
    } else if (tid == 16) {
        float s = 0.f;
#pragma unroll
        for (int w = 0; w < 8; w++) s += red[w][16];
        const float gamma = s + xproj_b[20];
        g_gs[m] = gamma / (1.f + expf(-gamma));
    }
}

// ---------------------------------------------------------------------------
// Per-chunk products of dA
// ---------------------------------------------------------------------------
__global__ void aprod_kernel()
{
    const int bc = blockIdx.x;
    const int n = threadIdx.x;
    const int b = bc / NCHUNK, c = bc % NCHUNK;
    float p = 1.f;
    const int base = (b * S_LEN + c * LCHUNK) * D_ST + n;
    for (int i = 0; i < LCHUNK; i++) p *= g_dA[base + i * D_ST];
    g_Ap[bc * D_ST + n] = p;
}

// ---------------------------------------------------------------------------
// Scan pass 1 (local, zero-init) with smem-staged dA
// ---------------------------------------------------------------------------
__global__ __launch_bounds__(256)
void scan_pass1(const float* __restrict__ Bm)
{
    __shared__ float s_a[LCHUNK * D_ST];    // 8 KB
    const int gid = blockIdx.x;
    const int d = ((gid & 7) << 8) + threadIdx.x;
    const int c = (gid >> 3) & (NCHUNK - 1);
    const int b = gid >> 7;
    const int m0 = b * S_LEN + c * LCHUNK;

    for (int i = threadIdx.x; i < LCHUNK * D_ST; i += 256) s_a[i] = g_dA[m0 * D_ST + i];
    __syncthreads();

    float dB[16];
#pragma unroll
    for (int q = 0; q < 4; q++) {
        float4 v = *(const float4*)(Bm + d * D_ST + 4 * q);
        dB[4*q+0] = sp_(v.x); dB[4*q+1] = sp_(v.y); dB[4*q+2] = sp_(v.z); dB[4*q+3] = sp_(v.w);
    }
    float h[16];
#pragma unroll
    for (int n = 0; n < 16; n++) h[n] = 0.f;

    const float* xp = g_xr + (size_t)m0 * 4096 + d;
    for (int i = 0; i < LCHUNK; i++) {
        const float u = __ldg(xp + (size_t)i * 4096);
#pragma unroll
        for (int q = 0; q < 4; q++) {
            float4 a4 = *(const float4*)(s_a + i * D_ST + 4 * q);
            h[4*q+0] = fmaf(h[4*q+0], a4.x, u * dB[4*q+0]);
            h[4*q+1] = fmaf(h[4*q+1], a4.y, u * dB[4*q+1]);
            h[4*q+2] = fmaf(h[4*q+2], a4.z, u * dB[4*q+2]);
            h[4*q+3] = fmaf(h[4*q+3], a4.w, u * dB[4*q+3]);
        }
    }
    const size_t o = ((size_t)(b * NCHUNK + c) * D_INNER + d) * D_ST;
#pragma unroll
    for (int q = 0; q < 4; q++)
        *(float4*)(g_hend + o + 4 * q) = make_float4(h[4*q], h[4*q+1], h[4*q+2], h[4*q+3]);
}

// ---------------------------------------------------------------------------
// Inter-chunk carry
// ---------------------------------------------------------------------------
__global__ void scan_carry()
{
    const int lin = blockIdx.x * 256 + threadIdx.x;
    const int n = lin & 15;
    const int d = (lin >> 4) & (D_INNER - 1);
    const int b = lin >> 15;
    float h = 0.f;
    for (int c = 0; c < NCHUNK; c++) {
        const size_t idx = ((size_t)(b * NCHUNK + c) * D_INNER + d) * D_ST + n;
        g_hin[idx] = h;
        h = h * g_Ap[(b * NCHUNK + c) * D_ST + n] + g_hend[idx];
    }
}

// ---------------------------------------------------------------------------
// Scan pass 2 -> g_y = tf32(y*silu(gamma)+res), with smem-staged dA & gs
// ---------------------------------------------------------------------------
__global__ __launch_bounds__(256)
void scan_pass2(const float* __restrict__ Bm, const float* __restrict__ Cm)
{
    __shared__ float s_a[LCHUNK * D_ST];
    __shared__ float s_g[LCHUNK];
    const int gid = blockIdx.x;
    const int d = ((gid & 7) << 8) + threadIdx.x;
    const int c = (gid >> 3) & (NCHUNK - 1);
    const int b = gid >> 7;
    const int m0 = b * S_LEN + c * LCHUNK;

    for (int i = threadIdx.x; i < LCHUNK * D_ST; i += 256) s_a[i] = g_dA[m0 * D_ST + i];
    for (int i = threadIdx.x; i < LCHUNK; i += 256) s_g[i] = g_gs[m0 + i];
    __syncthreads();

    float dB[16], dC[16];
#pragma unroll
    for (int q = 0; q < 4; q++) {
        float4 v = *(const float4*)(Bm + d * D_ST + 4 * q);
        dB[4*q+0] = sp_(v.x); dB[4*q+1] = sp_(v.y); dB[4*q+2] = sp_(v.z); dB[4*q+3] = sp_(v.w);
        float4 w = *(const float4*)(Cm + d * D_ST + 4 * q);
        dC[4*q+0] = w.x; dC[4*q+1] = w.y; dC[4*q+2] = w.z; dC[4*q+3] = w.w;
    }
    const size_t o = ((size_t)(b * NCHUNK + c) * D_INNER + d) * D_ST;
    float h[16];
#pragma unroll
    for (int q = 0; q < 4; q++) {
        float4 v = *(const float4*)(g_hin + o + 4 * q);
        h[4*q+0] = v.x; h[4*q+1] = v.y; h[4*q+2] = v.z; h[4*q+3] = v.w;
    }

    const float* xp = g_xr + (size_t)m0 * 4096 + d;
    const float* rp = g_xr + (size_t)m0 * 4096 + D_INNER + d;
    float* yp = g_y + (size_t)m0 * D_INNER + d;

    for (int i = 0; i < LCHUNK; i++) {
        const float u = __ldg(xp + (size_t)i * 4096);
        float y = 0.f;
#pragma unroll
        for (int q = 0; q < 4; q++) {
            float4 a4 = *(const float4*)(s_a + i * D_ST + 4 * q);
            h[4*q+0] = fmaf(h[4*q+0], a4.x, u * dB[4*q+0]);
            h[4*q+1] = fmaf(h[4*q+1], a4.y, u * dB[4*q+1]);
            h[4*q+2] = fmaf(h[4*q+2], a4.z, u * dB[4*q+2]);
            h[4*q+3] = fmaf(h[4*q+3], a4.w, u * dB[4*q+3]);
            y = fmaf(h[4*q+0], dC[4*q+0], y);
            y = fmaf(h[4*q+1], dC[4*q+1], y);
            y = fmaf(h[4*q+2], dC[4*q+2], y);
            y = fmaf(h[4*q+3], dC[4*q+3], y);
        }
        yp[(size_t)i * D_INNER] = tf32r(fmaf(y, s_g[i], __ldg(rp + (size_t)i * 4096)));
    }
}

// ---------------------------------------------------------------------------
// Launch
// ---------------------------------------------------------------------------
extern "C" void kernel_launch(void* const* d_in, const int* in_sizes, int n_in,
                              void* d_out, int out_size)
{
    const float* x       = (const float*)d_in[0];
    const float* in_w    = (const float*)d_in[1];
    const float* in_b    = (const float*)d_in[2];
    const float* conv_w  = (const float*)d_in[3];
    const float* conv_b  = (const float*)d_in[4];
    const float* xproj_w = (const float*)d_in[5];
    const float* xproj_b = (const float*)d_in[6];
    const float* dt_w    = (const float*)d_in[7];
    const float* dt_b    = (const float*)d_in[8];
    const float* A       = (const float*)d_in[9];
    const float* Bm      = (const float*)d_in[10];
    const float* Cm      = (const float*)d_in[11];
    const float* out_w   = (const float*)d_in[12];
    const float* out_b   = (const float*)d_in[13];
    float* out = (float*)d_out;

    float *xr, *y, *xt, *w1t, *w2t;
    cudaGetSymbolAddress((void**)&xr,  g_xr);
    cudaGetSymbolAddress((void**)&y,   g_y);
    cudaGetSymbolAddress((void**)&xt,  g_xt);
    cudaGetSymbolAddress((void**)&w1t, g_w1t);
    cudaGetSymbolAddress((void**)&w2t, g_w2t);

    cudaFuncSetAttribute(gemm_mma<1024, 4096>, cudaFuncAttributeMaxDynamicSharedMemorySize, GSMEM_BYTES);
    cudaFuncSetAttribute(gemm_mma<2048, 1024>, cudaFuncAttributeMaxDynamicSharedMemorySize, GSMEM_BYTES);

    // round inputs to tf32 (rna)
    k_tf32round<<<1024, 256>>>((const float4*)x,     (float4*)xt,  (M_ROWS * DIM_) / 4);
    k_tf32round<<<1024, 256>>>((const float4*)in_w,  (float4*)w1t, (4096 * DIM_) / 4);
    k_tf32round<<<1024, 256>>>((const float4*)out_w, (float4*)w2t, (DIM_ * D_INNER) / 4);

    // GEMM1: g_xr = x @ in_w^T + in_b     [8192, 4096]
    gemm_mma<1024, 4096><<<dim3(4096 / 128, M_ROWS / 128), 256, GSMEM_BYTES>>>(xt, w1t, in_b, xr);

    // conv + projections -> dA, silu(gamma)
    conv_proj<<<M_ROWS, 256>>>(conv_w, conv_b, xproj_w, xproj_b, dt_w, dt_b, A);

    // chunked scan
    aprod_kernel<<<BATCH * NCHUNK, D_ST>>>();
    scan_pass1<<<BATCH * NCHUNK * (D_INNER / 256), 256>>>(Bm);
    scan_carry<<<(BATCH * D_INNER * D_ST) / 256, 256>>>();
    scan_pass2<<<BATCH * NCHUNK * (D_INNER / 256), 256>>>(Bm, Cm);

    // GEMM2: out = g_y @ out_w^T + out_b  [8192, 1024]
    gemm_mma<2048, 1024><<<dim3(1024 / 128, M_ROWS / 128), 256, GSMEM_BYTES>>>(y, w2t, out_b, out);
}

// round 5
// speedup vs baseline: 2.8660x; 1.0341x over previous
#include <cuda_runtime.h>
#include <cstdint>
#include <math.h>

// ---------------------------------------------------------------------------
// Problem constants
// ---------------------------------------------------------------------------
#define S_LEN   2048
#define BATCH   4
#define DIM_    1024
#define D_INNER 2048
#define D_ST    16
#define M_ROWS  (BATCH * S_LEN)      // 8192
#define NCHUNK  16
#define LCHUNK  (S_LEN / NCHUNK)     // 128

// ---------------------------------------------------------------------------
// Scratch (static __device__ — no allocations allowed)
// ---------------------------------------------------------------------------
__device__ float g_xr [(size_t)M_ROWS * 4096];              // [m][0:2048)=x_copy, [2048:4096)=res
__device__ float g_y  [(size_t)M_ROWS * D_INNER];           // gated scan output (tf32-rounded)
__device__ float g_dA [M_ROWS * D_ST];
__device__ float g_gs [M_ROWS];
__device__ float g_Ap [BATCH * NCHUNK * D_ST];
__device__ float g_hend[(size_t)BATCH * NCHUNK * D_INNER * D_ST];
__device__ float g_hin [(size_t)BATCH * NCHUNK * D_INNER * D_ST];
__device__ float g_xt [(size_t)M_ROWS * DIM_];              // tf32-rounded x
__device__ float g_w1t[(size_t)4096 * DIM_];                // tf32-rounded in_w
__device__ float g_w2t[(size_t)DIM_ * D_INNER];             // tf32-rounded out_w

// ---------------------------------------------------------------------------
// Helpers
// ---------------------------------------------------------------------------
__device__ __forceinline__ float sp_(float x) { return x > 20.f ? x : log1pf(expf(x)); }

__device__ __forceinline__ float tf32r(float x) {
    uint32_t r; asm("cvt.rna.tf32.f32 %0, %1;" : "=r"(r) : "f"(x));
    return __uint_as_float(r);
}
__device__ __forceinline__ uint32_t s2u(const void* p) {
    uint32_t a;
    asm("{ .reg .u64 t; cvta.to.shared.u64 t, %1; cvt.u32.u64 %0, t; }" : "=r"(a) : "l"(p));
    return a;
}
__device__ __forceinline__ void cpa16(uint32_t dst, const float* src) {
    asm volatile("cp.async.cg.shared.global [%0], [%1], 16;" :: "r"(dst), "l"(src) : "memory");
}
__device__ __forceinline__ void mma8(float* d, const uint32_t* a, const uint32_t* b) {
    asm volatile("mma.sync.aligned.m16n8k8.row.col.f32.tf32.tf32.f32 "
        "{%0,%1,%2,%3}, {%4,%5,%6,%7}, {%8,%9}, {%0,%1,%2,%3};"
        : "+f"(d[0]), "+f"(d[1]), "+f"(d[2]), "+f"(d[3])
        : "r"(a[0]), "r"(a[1]), "r"(a[2]), "r"(a[3]), "r"(b[0]), "r"(b[1]));
}

// ---------------------------------------------------------------------------
// tf32 round-to-nearest conversion (float4 grid-stride)
// ---------------------------------------------------------------------------
__global__ void k_tf32round(const float4* __restrict__ in, float4* __restrict__ out, int n4)
{
    for (int i = blockIdx.x * blockDim.x + threadIdx.x; i < n4; i += gridDim.x * blockDim.x) {
        float4 v = in[i];
        v.x = tf32r(v.x); v.y = tf32r(v.y); v.z = tf32r(v.z); v.w = tf32r(v.w);
        out[i] = v;
    }
}

// ---------------------------------------------------------------------------
// TF32 mma.sync GEMM:  C[M,NN] = A[M,K] @ W[NN,K]^T + bias
//  - 256x128 CTA tile, K-tile 64, 2-stage cp.async double buffer
//  - 8 warps (4m x 2n), 64x64 warp tile -> halves smem bytes/MAC vs 32x64
//  - rows padded to 68 floats (68 mod 32 = 4 -> conflict-free LDS.32 frags,
//    272B rows keep cp.async 16B alignment)
// ---------------------------------------------------------------------------
#define RP      68
#define A_STG   (256 * RP)                    // floats per A stage
#define B_STG   (128 * RP)                    // floats per B stage
#define STG_F   (A_STG + B_STG)               // 26112 floats per stage
#define GSMEM_BYTES (2 * STG_F * 4)           // 208896

template<int KDIM, int NN>
__global__ __launch_bounds__(256)
void gemm_mma(const float* __restrict__ A, const float* __restrict__ W,
              const float* __restrict__ bias, float* __restrict__ C)
{
    constexpr int T = KDIM / 64;
    extern __shared__ __align__(16) float smem[];
    const uint32_t sbu = s2u(smem);

    const int tid  = threadIdx.x;
    const int lane = tid & 31, warp = tid >> 5;
    const int warpM = warp & 3, warpN = warp >> 2;
    const int gID = lane >> 2, tig = lane & 3;
    const int mBase = blockIdx.y * 256, nBase = blockIdx.x * 128;

    float acc[4][8][4];
#pragma unroll
    for (int i = 0; i < 4; i++)
#pragma unroll
        for (int j = 0; j < 8; j++)
#pragma unroll
            for (int q = 0; q < 4; q++) acc[i][j][q] = 0.f;

    // ---- async tile loader: A 256x64f (4096 16B-chunks), B 128x64f (2048) ----
    auto load_stage = [&](int t, int s) {
        const int k0 = t * 64;
        const uint32_t sa = sbu + (uint32_t)(s * STG_F) * 4u;
        const uint32_t sb = sa + (uint32_t)A_STG * 4u;
#pragma unroll
        for (int i = 0; i < 16; i++) {
            const int c = i * 256 + tid;               // 0..4095
            const int row = c >> 4, c16 = c & 15;
            cpa16(sa + (uint32_t)(row * RP + c16 * 4) * 4u,
                  A + (size_t)(mBase + row) * KDIM + k0 + c16 * 4);
        }
#pragma unroll
        for (int i = 0; i < 8; i++) {
            const int c = i * 256 + tid;               // 0..2047
            const int row = c >> 4, c16 = c & 15;
            cpa16(sb + (uint32_t)(row * RP + c16 * 4) * 4u,
                  W + (size_t)(nBase + row) * KDIM + k0 + c16 * 4);
        }
        asm volatile("cp.async.commit_group;" ::: "memory");
    };

    load_stage(0, 0);
    load_stage(1, 1);

    for (int t = 0; t < T; t++) {
        const int s = t & 1;
        if (t + 1 < T) { asm volatile("cp.async.wait_group 1;" ::: "memory"); }
        else           { asm volatile("cp.async.wait_group 0;" ::: "memory"); }
        __syncthreads();

        const float* arow = smem + s * STG_F + (warpM * 64) * RP;
        const float* brow = smem + s * STG_F + A_STG + (warpN * 64) * RP;
#pragma unroll
        for (int kk = 0; kk < 8; kk++) {
            const int k0 = kk * 8;
            uint32_t a[4][4], b[8][2];
#pragma unroll
            for (int mi = 0; mi < 4; mi++) {
                const float* ap = arow + (mi * 16 + gID) * RP;
                a[mi][0] = __float_as_uint(ap[k0 + tig]);
                a[mi][1] = __float_as_uint(ap[8 * RP + k0 + tig]);
                a[mi][2] = __float_as_uint(ap[k0 + tig + 4]);
                a[mi][3] = __float_as_uint(ap[8 * RP + k0 + tig + 4]);
            }
#pragma unroll
            for (int j = 0; j < 8; j++) {
                const float* bp = brow + (j * 8 + gID) * RP;
                b[j][0] = __float_as_uint(bp[k0 + tig]);
                b[j][1] = __float_as_uint(bp[k0 + tig + 4]);
            }
#pragma unroll
            for (int mi = 0; mi < 4; mi++)
#pragma unroll
                for (int j = 0; j < 8; j++)
                    mma8(acc[mi][j], a[mi], b[j]);
        }
        __syncthreads();                               // stage s free for refill
        if (t + 2 < T) load_stage(t + 2, s);
    }

    // ---- epilogue ----
#pragma unroll
    for (int mi = 0; mi < 4; mi++) {
        const int row0 = mBase + warpM * 64 + mi * 16 + gID;
        const int col0 = nBase + warpN * 64 + tig * 2;
#pragma unroll
        for (int j = 0; j < 8; j++) {
            const int cc = col0 + j * 8;
            const float b0 = __ldg(bias + cc), b1 = __ldg(bias + cc + 1);
            *(float2*)(C + (size_t)row0 * NN + cc) =
                make_float2(acc[mi][j][0] + b0, acc[mi][j][1] + b1);
            *(float2*)(C + (size_t)(row0 + 8) * NN + cc) =
                make_float2(acc[mi][j][2] + b0, acc[mi][j][3] + b1);
        }
    }
}

// ---------------------------------------------------------------------------
// Fused conv(depthwise,4) + gamma/delta projections -> dA, silu(gamma)
// ---------------------------------------------------------------------------
__global__ __launch_bounds__(256)
void conv_proj(const float* __restrict__ conv_w, const float* __restrict__ conv_b,
               const float* __restrict__ xproj_w, const float* __restrict__ xproj_b,
               const float* __restrict__ dt_w, const float* __restrict__ dt_b,
               const float* __restrict__ Avec)
{
    const int m = blockIdx.x;
    const int b = m >> 11, t = m & (S_LEN - 1);
    const int tid = threadIdx.x, lane = tid & 31, wid = tid >> 5;
    const float* xc = g_xr + (size_t)b * S_LEN * 4096;
    const float* w20 = xproj_w + 20 * D_INNER;

    float part[17];
#pragma unroll
    for (int r = 0; r < 17; r++) part[r] = 0.f;

#pragma unroll
    for (int g = 0; g < 2; g++) {
        const int d = (tid << 3) + (g << 2);
        float wmat[4][4];
#pragma unroll
        for (int q = 0; q < 4; q++) {
            float4 cwv = *(const float4*)(conv_w + (d + q) * 4);
            wmat[q][0] = cwv.x; wmat[q][1] = cwv.y; wmat[q][2] = cwv.z; wmat[q][3] = cwv.w;
        }
        float4 cbv = *(const float4*)(conv_b + d);
        float cs[4] = {cbv.x, cbv.y, cbv.z, cbv.w};
#pragma unroll
        for (int k = 0; k < 4; k++) {
            const int tk = t - 1 + k;
            if (tk >= 0 && tk < S_LEN) {
                float4 xv = *(const float4*)(xc + (size_t)tk * 4096 + d);
                cs[0] = fmaf(wmat[0][k], xv.x, cs[0]);
                cs[1] = fmaf(wmat[1][k], xv.y, cs[1]);
                cs[2] = fmaf(wmat[2][k], xv.z, cs[2]);
                cs[3] = fmaf(wmat[3][k], xv.w, cs[3]);
            }
        }
        float4 wg = *(const float4*)(w20 + d);
        part[16] += cs[0]*wg.x + cs[1]*wg.y + cs[2]*wg.z + cs[3]*wg.w;
#pragma unroll
        for (int n = 0; n < 16; n++) {
            float4 wv = *(const float4*)(dt_w + n * D_INNER + d);
            part[n] = fmaf(cs[0], wv.x, fmaf(cs[1], wv.y,
                      fmaf(cs[2], wv.z, fmaf(cs[3], wv.w, part[n]))));
        }
    }

    __shared__ float red[8][17];
#pragma unroll
    for (int r = 0; r < 17; r++) {
        float v = part[r];
#pragma unroll
        for (int o = 16; o > 0; o >>= 1) v += __shfl_down_sync(0xffffffffu, v, o);
        if (lane == 0) red[wid][r] = v;
    }
    __syncthreads();
    if (tid < 16) {
        float s = 0.f;
#pragma unroll
        for (int w = 0; w < 8; w++) s += red[w][tid];
        const float delta = sp_(s + dt_b[tid]);
        const float spA   = sp_(Avec[tid]);
        g_dA[m * D_ST + tid] = expf(-delta * spA);
    } else if (tid == 16) {
        float s = 0.f;
#pragma unroll
        for (int w = 0; w < 8; w++) s += red[w][16];
        const float gamma = s + xproj_b[20];
        g_gs[m] = gamma / (1.f + expf(-gamma));
    }
}

// ---------------------------------------------------------------------------
// Per-chunk products of dA
// ---------------------------------------------------------------------------
__global__ void aprod_kernel()
{
    const int bc = blockIdx.x;
    const int n = threadIdx.x;
    const int b = bc / NCHUNK, c = bc % NCHUNK;
    float p = 1.f;
    const int base = (b * S_LEN + c * LCHUNK) * D_ST + n;
    for (int i = 0; i < LCHUNK; i++) p *= g_dA[base + i * D_ST];
    g_Ap[bc * D_ST + n] = p;
}

// ---------------------------------------------------------------------------
// Scan pass 1 (local, zero-init) with smem-staged dA
// ---------------------------------------------------------------------------
__global__ __launch_bounds__(256)
void scan_pass1(const float* __restrict__ Bm)
{
    __shared__ float s_a[LCHUNK * D_ST];    // 8 KB
    const int gid = blockIdx.x;
    const int d = ((gid & 7) << 8) + threadIdx.x;
    const int c = (gid >> 3) & (NCHUNK - 1);
    const int b = gid >> 7;
    const int m0 = b * S_LEN + c * LCHUNK;

    for (int i = threadIdx.x; i < LCHUNK * D_ST; i += 256) s_a[i] = g_dA[m0 * D_ST + i];
    __syncthreads();

    float dB[16];
#pragma unroll
    for (int q = 0; q < 4; q++) {
        float4 v = *(const float4*)(Bm + d * D_ST + 4 * q);
        dB[4*q+0] = sp_(v.x); dB[4*q+1] = sp_(v.y); dB[4*q+2] = sp_(v.z); dB[4*q+3] = sp_(v.w);
    }
    float h[16];
#pragma unroll
    for (int n = 0; n < 16; n++) h[n] = 0.f;

    const float* xp = g_xr + (size_t)m0 * 4096 + d;
    for (int i = 0; i < LCHUNK; i++) {
        const float u = __ldg(xp + (size_t)i * 4096);
#pragma unroll
        for (int q = 0; q < 4; q++) {
            float4 a4 = *(const float4*)(s_a + i * D_ST + 4 * q);
            h[4*q+0] = fmaf(h[4*q+0], a4.x, u * dB[4*q+0]);
            h[4*q+1] = fmaf(h[4*q+1], a4.y, u * dB[4*q+1]);
            h[4*q+2] = fmaf(h[4*q+2], a4.z, u * dB[4*q+2]);
            h[4*q+3] = fmaf(h[4*q+3], a4.w, u * dB[4*q+3]);
        }
    }
    const size_t o = ((size_t)(b * NCHUNK + c) * D_INNER + d) * D_ST;
#pragma unroll
    for (int q = 0; q < 4; q++)
        *(float4*)(g_hend + o + 4 * q) = make_float4(h[4*q], h[4*q+1], h[4*q+2], h[4*q+3]);
}

// ---------------------------------------------------------------------------
// Inter-chunk carry
// ---------------------------------------------------------------------------
__global__ void scan_carry()
{
    const int lin = blockIdx.x * 256 + threadIdx.x;
    const int n = lin & 15;
    const int d = (lin >> 4) & (D_INNER - 1);
    const int b = lin >> 15;
    float h = 0.f;
    for (int c = 0; c < NCHUNK; c++) {
        const size_t idx = ((size_t)(b * NCHUNK + c) * D_INNER + d) * D_ST + n;
        g_hin[idx] = h;
        h = h * g_Ap[(b * NCHUNK + c) * D_ST + n] + g_hend[idx];
    }
}

// ---------------------------------------------------------------------------
// Scan pass 2 -> g_y = tf32(y*silu(gamma)+res), with smem-staged dA & gs
// ---------------------------------------------------------------------------
__global__ __launch_bounds__(256)
void scan_pass2(const float* __restrict__ Bm, const float* __restrict__ Cm)
{
    __shared__ float s_a[LCHUNK * D_ST];
    __shared__ float s_g[LCHUNK];
    const int gid = blockIdx.x;
    const int d = ((gid & 7) << 8) + threadIdx.x;
    const int c = (gid >> 3) & (NCHUNK - 1);
    const int b = gid >> 7;
    const int m0 = b * S_LEN + c * LCHUNK;

    for (int i = threadIdx.x; i < LCHUNK * D_ST; i += 256) s_a[i] = g_dA[m0 * D_ST + i];
    for (int i = threadIdx.x; i < LCHUNK; i += 256) s_g[i] = g_gs[m0 + i];
    __syncthreads();

    float dB[16], dC[16];
#pragma unroll
    for (int q = 0; q < 4; q++) {
        float4 v = *(const float4*)(Bm + d * D_ST + 4 * q);
        dB[4*q+0] = sp_(v.x); dB[4*q+1] = sp_(v.y); dB[4*q+2] = sp_(v.z); dB[4*q+3] = sp_(v.w);
        float4 w = *(const float4*)(Cm + d * D_ST + 4 * q);
        dC[4*q+0] = w.x; dC[4*q+1] = w.y; dC[4*q+2] = w.z; dC[4*q+3] = w.w;
    }
    const size_t o = ((size_t)(b * NCHUNK + c) * D_INNER + d) * D_ST;
    float h[16];
#pragma unroll
    for (int q = 0; q < 4; q++) {
        float4 v = *(const float4*)(g_hin + o + 4 * q);
        h[4*q+0] = v.x; h[4*q+1] = v.y; h[4*q+2] = v.z; h[4*q+3] = v.w;
    }

    const float* xp = g_xr + (size_t)m0 * 4096 + d;
    const float* rp = g_xr + (size_t)m0 * 4096 + D_INNER + d;
    float* yp = g_y + (size_t)m0 * D_INNER + d;

    for (int i = 0; i < LCHUNK; i++) {
        const float u = __ldg(xp + (size_t)i * 4096);
        float y = 0.f;
#pragma unroll
        for (int q = 0; q < 4; q++) {
            float4 a4 = *(const float4*)(s_a + i * D_ST + 4 * q);
            h[4*q+0] = fmaf(h[4*q+0], a4.x, u * dB[4*q+0]);
            h[4*q+1] = fmaf(h[4*q+1], a4.y, u * dB[4*q+1]);
            h[4*q+2] = fmaf(h[4*q+2], a4.z, u * dB[4*q+2]);
            h[4*q+3] = fmaf(h[4*q+3], a4.w, u * dB[4*q+3]);
            y = fmaf(h[4*q+0], dC[4*q+0], y);
            y = fmaf(h[4*q+1], dC[4*q+1], y);
            y = fmaf(h[4*q+2], dC[4*q+2], y);
            y = fmaf(h[4*q+3], dC[4*q+3], y);
        }
        yp[(size_t)i * D_INNER] = tf32r(fmaf(y, s_g[i], __ldg(rp + (size_t)i * 4096)));
    }
}

// ---------------------------------------------------------------------------
// Launch
// ---------------------------------------------------------------------------
extern "C" void kernel_launch(void* const* d_in, const int* in_sizes, int n_in,
                              void* d_out, int out_size)
{
    const float* x       = (const float*)d_in[0];
    const float* in_w    = (const float*)d_in[1];
    const float* in_b    = (const float*)d_in[2];
    const float* conv_w  = (const float*)d_in[3];
    const float* conv_b  = (const float*)d_in[4];
    const float* xproj_w = (const float*)d_in[5];
    const float* xproj_b = (const float*)d_in[6];
    const float* dt_w    = (const float*)d_in[7];
    const float* dt_b    = (const float*)d_in[8];
    const float* A       = (const float*)d_in[9];
    const float* Bm      = (const float*)d_in[10];
    const float* Cm      = (const float*)d_in[11];
    const float* out_w   = (const float*)d_in[12];
    const float* out_b   = (const float*)d_in[13];
    float* out = (float*)d_out;

    float *xr, *y, *xt, *w1t, *w2t;
    cudaGetSymbolAddress((void**)&xr,  g_xr);
    cudaGetSymbolAddress((void**)&y,   g_y);
    cudaGetSymbolAddress((void**)&xt,  g_xt);
    cudaGetSymbolAddress((void**)&w1t, g_w1t);
    cudaGetSymbolAddress((void**)&w2t, g_w2t);

    cudaFuncSetAttribute(gemm_mma<1024, 4096>, cudaFuncAttributeMaxDynamicSharedMemorySize, GSMEM_BYTES);
    cudaFuncSetAttribute(gemm_mma<2048, 1024>, cudaFuncAttributeMaxDynamicSharedMemorySize, GSMEM_BYTES);

    // round inputs to tf32 (rna)
    k_tf32round<<<1024, 256>>>((const float4*)x,     (float4*)xt,  (M_ROWS * DIM_) / 4);
    k_tf32round<<<1024, 256>>>((const float4*)in_w,  (float4*)w1t, (4096 * DIM_) / 4);
    k_tf32round<<<1024, 256>>>((const float4*)out_w, (float4*)w2t, (DIM_ * D_INNER) / 4);

    // GEMM1: g_xr = x @ in_w^T + in_b     [8192, 4096]
    gemm_mma<1024, 4096><<<dim3(4096 / 128, M_ROWS / 256), 256, GSMEM_BYTES>>>(xt, w1t, in_b, xr);

    // conv + projections -> dA, silu(gamma)
    conv_proj<<<M_ROWS, 256>>>(conv_w, conv_b, xproj_w, xproj_b, dt_w, dt_b, A);

    // chunked scan
    aprod_kernel<<<BATCH * NCHUNK, D_ST>>>();
    scan_pass1<<<BATCH * NCHUNK * (D_INNER / 256), 256>>>(Bm);
    scan_carry<<<(BATCH * D_INNER * D_ST) / 256, 256>>>();
    scan_pass2<<<BATCH * NCHUNK * (D_INNER / 256), 256>>>(Bm, Cm);

    // GEMM2: out = g_y @ out_w^T + out_b  [8192, 1024]
    gemm_mma<2048, 1024><<<dim3(1024 / 128, M_ROWS / 256), 256, GSMEM_BYTES>>>(y, w2t, out_b, out);
}

// round 6
// speedup vs baseline: 3.2971x; 1.1504x over previous
#include <cuda_runtime.h>
#include <cstdint>
#include <math.h>

// ---------------------------------------------------------------------------
// Problem constants
// ---------------------------------------------------------------------------
#define S_LEN   2048
#define BATCH   4
#define DIM_    1024
#define D_INNER 2048
#define D_ST    16
#define M_ROWS  (BATCH * S_LEN)      // 8192
#define NCHUNK  16
#define LCHUNK  (S_LEN / NCHUNK)     // 128

// ---------------------------------------------------------------------------
// Scratch (static __device__ — no allocations allowed)
// ---------------------------------------------------------------------------
__device__ float g_xr [(size_t)M_ROWS * 4096];              // [m][0:2048)=x_copy, [2048:4096)=res
__device__ float g_y  [(size_t)M_ROWS * D_INNER];           // gated scan output (tf32-rounded)
__device__ float g_dA [M_ROWS * D_ST];
__device__ float g_gs [M_ROWS];
__device__ float g_Ap [BATCH * NCHUNK * D_ST];
__device__ float g_hend[(size_t)BATCH * NCHUNK * D_INNER * D_ST];
__device__ float g_hin [(size_t)BATCH * NCHUNK * D_INNER * D_ST];
__device__ float g_xt [(size_t)M_ROWS * DIM_];              // tf32-rounded x
__device__ float g_w1t[(size_t)4096 * DIM_];                // tf32-rounded in_w
__device__ float g_w2t[(size_t)DIM_ * D_INNER];             // tf32-rounded out_w

// ---------------------------------------------------------------------------
// Helpers
// ---------------------------------------------------------------------------
__device__ __forceinline__ float sp_(float x) { return x > 20.f ? x : log1pf(expf(x)); }

__device__ __forceinline__ float tf32r(float x) {
    uint32_t r; asm("cvt.rna.tf32.f32 %0, %1;" : "=r"(r) : "f"(x));
    return __uint_as_float(r);
}
__device__ __forceinline__ uint32_t s2u(const void* p) {
    uint32_t a;
    asm("{ .reg .u64 t; cvta.to.shared.u64 t, %1; cvt.u32.u64 %0, t; }" : "=r"(a) : "l"(p));
    return a;
}
__device__ __forceinline__ void cpa16(uint32_t dst, const float* src) {
    asm volatile("cp.async.cg.shared.global [%0], [%1], 16;" :: "r"(dst), "l"(src) : "memory");
}
__device__ __forceinline__ void mma8(float* d, const uint32_t* a, const uint32_t* b) {
    asm volatile("mma.sync.aligned.m16n8k8.row.col.f32.tf32.tf32.f32 "
        "{%0,%1,%2,%3}, {%4,%5,%6,%7}, {%8,%9}, {%0,%1,%2,%3};"
        : "+f"(d[0]), "+f"(d[1]), "+f"(d[2]), "+f"(d[3])
        : "r"(a[0]), "r"(a[1]), "r"(a[2]), "r"(a[3]), "r"(b[0]), "r"(b[1]));
}

// ---------------------------------------------------------------------------
// tf32 round-to-nearest conversion (float4 grid-stride)
// ---------------------------------------------------------------------------
__global__ void k_tf32round(const float4* __restrict__ in, float4* __restrict__ out, int n4)
{
    for (int i = blockIdx.x * blockDim.x + threadIdx.x; i < n4; i += gridDim.x * blockDim.x) {
        float4 v = in[i];
        v.x = tf32r(v.x); v.y = tf32r(v.y); v.z = tf32r(v.z); v.w = tf32r(v.w);
        out[i] = v;
    }
}

// ---------------------------------------------------------------------------
// TF32 mma.sync GEMM:  C[M,NN] = A[M,K] @ W[NN,K]^T + bias
//  - 256x128 CTA tile, K-tile 64, 2-stage cp.async double buffer
//  - 8 warps (4m x 2n), 64x64 warp tile
//  - register-level fragment double buffering across k-steps (hide LDS latency)
//  - rows padded to 68 floats: conflict-free LDS.32 frags, 16B-aligned cp.async
// ---------------------------------------------------------------------------
#define RP      68
#define A_STG   (256 * RP)
#define B_STG   (128 * RP)
#define STG_F   (A_STG + B_STG)               // 26112 floats per stage
#define GSMEM_BYTES (2 * STG_F * 4)           // 208896

template<int KDIM, int NN>
__global__ __launch_bounds__(256)
void gemm_mma(const float* __restrict__ A, const float* __restrict__ W,
              const float* __restrict__ bias, float* __restrict__ C)
{
    constexpr int T = KDIM / 64;
    extern __shared__ __align__(16) float smem[];
    const uint32_t sbu = s2u(smem);

    const int tid  = threadIdx.x;
    const int lane = tid & 31, warp = tid >> 5;
    const int warpM = warp & 3, warpN = warp >> 2;
    const int gID = lane >> 2, tig = lane & 3;
    const int mBase = blockIdx.y * 256, nBase = blockIdx.x * 128;

    float acc[4][8][4];
#pragma unroll
    for (int i = 0; i < 4; i++)
#pragma unroll
        for (int j = 0; j < 8; j++)
#pragma unroll
            for (int q = 0; q < 4; q++) acc[i][j][q] = 0.f;

    // ---- async tile loader: A 256x64f (4096 16B-chunks), B 128x64f (2048) ----
    auto load_stage = [&](int t, int s) {
        const int k0 = t * 64;
        const uint32_t sa = sbu + (uint32_t)(s * STG_F) * 4u;
        const uint32_t sb = sa + (uint32_t)A_STG * 4u;
#pragma unroll
        for (int i = 0; i < 16; i++) {
            const int c = i * 256 + tid;
            const int row = c >> 4, c16 = c & 15;
            cpa16(sa + (uint32_t)(row * RP + c16 * 4) * 4u,
                  A + (size_t)(mBase + row) * KDIM + k0 + c16 * 4);
        }
#pragma unroll
        for (int i = 0; i < 8; i++) {
            const int c = i * 256 + tid;
            const int row = c >> 4, c16 = c & 15;
            cpa16(sb + (uint32_t)(row * RP + c16 * 4) * 4u,
                  W + (size_t)(nBase + row) * KDIM + k0 + c16 * 4);
        }
        asm volatile("cp.async.commit_group;" ::: "memory");
    };

    load_stage(0, 0);
    load_stage(1, 1);

    uint32_t afr[2][4][4], bfr[2][8][2];

    for (int t = 0; t < T; t++) {
        const int s = t & 1;
        if (t + 1 < T) { asm volatile("cp.async.wait_group 1;" ::: "memory"); }
        else           { asm volatile("cp.async.wait_group 0;" ::: "memory"); }
        __syncthreads();

        const float* arow = smem + s * STG_F + (warpM * 64) * RP;
        const float* brow = smem + s * STG_F + A_STG + (warpN * 64) * RP;

        auto ldfrag = [&](int kk, int pb) {
            const int k0 = kk * 8;
#pragma unroll
            for (int mi = 0; mi < 4; mi++) {
                const float* ap = arow + (mi * 16 + gID) * RP;
                afr[pb][mi][0] = __float_as_uint(ap[k0 + tig]);
                afr[pb][mi][1] = __float_as_uint(ap[8 * RP + k0 + tig]);
                afr[pb][mi][2] = __float_as_uint(ap[k0 + tig + 4]);
                afr[pb][mi][3] = __float_as_uint(ap[8 * RP + k0 + tig + 4]);
            }
#pragma unroll
            for (int j = 0; j < 8; j++) {
                const float* bp = brow + (j * 8 + gID) * RP;
                bfr[pb][j][0] = __float_as_uint(bp[k0 + tig]);
                bfr[pb][j][1] = __float_as_uint(bp[k0 + tig + 4]);
            }
        };

        ldfrag(0, 0);
#pragma unroll
        for (int kk = 0; kk < 8; kk++) {
            const int cur = kk & 1;
            if (kk < 7) ldfrag(kk + 1, cur ^ 1);   // prefetch next k-step frags
#pragma unroll
            for (int mi = 0; mi < 4; mi++)
#pragma unroll
                for (int j = 0; j < 8; j++)
                    mma8(acc[mi][j], afr[cur][mi], bfr[cur][j]);
        }
        __syncthreads();                           // stage s free for refill
        if (t + 2 < T) load_stage(t + 2, s);
    }

    // ---- epilogue ----
#pragma unroll
    for (int mi = 0; mi < 4; mi++) {
        const int row0 = mBase + warpM * 64 + mi * 16 + gID;
        const int col0 = nBase + warpN * 64 + tig * 2;
#pragma unroll
        for (int j = 0; j < 8; j++) {
            const int cc = col0 + j * 8;
            const float b0 = __ldg(bias + cc), b1 = __ldg(bias + cc + 1);
            *(float2*)(C + (size_t)row0 * NN + cc) =
                make_float2(acc[mi][j][0] + b0, acc[mi][j][1] + b1);
            *(float2*)(C + (size_t)(row0 + 8) * NN + cc) =
                make_float2(acc[mi][j][2] + b0, acc[mi][j][3] + b1);
        }
    }
}

// ---------------------------------------------------------------------------
// Fused conv(depthwise,4) + gamma/delta projections -> dA, silu(gamma)
// 4 tokens per block: amortizes dt_w/conv_w/x reads 4x.
// ---------------------------------------------------------------------------
__global__ __launch_bounds__(256)
void conv_proj(const float* __restrict__ conv_w, const float* __restrict__ conv_b,
               const float* __restrict__ xproj_w, const float* __restrict__ xproj_b,
               const float* __restrict__ dt_w, const float* __restrict__ dt_b,
               const float* __restrict__ Avec)
{
    const int m0 = blockIdx.x * 4;                  // first token row
    const int b = m0 >> 11, t0 = m0 & (S_LEN - 1);
    const int tid = threadIdx.x, lane = tid & 31, wid = tid >> 5;
    const float* xc = g_xr + (size_t)b * S_LEN * 4096;
    const float* w20 = xproj_w + 20 * D_INNER;

    float part[4][17];
#pragma unroll
    for (int tok = 0; tok < 4; tok++)
#pragma unroll
        for (int r = 0; r < 17; r++) part[tok][r] = 0.f;

#pragma unroll
    for (int g = 0; g < 2; g++) {
        const int d = (tid << 3) + (g << 2);
        float wmat[4][4];
#pragma unroll
        for (int q = 0; q < 4; q++) {
            float4 cwv = *(const float4*)(conv_w + (d + q) * 4);
            wmat[q][0] = cwv.x; wmat[q][1] = cwv.y; wmat[q][2] = cwv.z; wmat[q][3] = cwv.w;
        }
        float4 cbv = *(const float4*)(conv_b + d);
        float cs[4][4];
#pragma unroll
        for (int tok = 0; tok < 4; tok++) {
            cs[tok][0] = cbv.x; cs[tok][1] = cbv.y; cs[tok][2] = cbv.z; cs[tok][3] = cbv.w;
        }
        // taps for tokens t0..t0+3 span rows t0-1 .. t0+5
#pragma unroll
        for (int rr = -1; rr <= 5; rr++) {
            const int tk = t0 + rr;
            if (tk >= 0 && tk < S_LEN) {
                float4 xv = *(const float4*)(xc + (size_t)tk * 4096 + d);
#pragma unroll
                for (int tok = 0; tok < 4; tok++) {
                    const int k = rr - tok + 1;     // compile-time per (rr,tok)
                    if (k >= 0 && k < 4) {
                        cs[tok][0] = fmaf(wmat[0][k], xv.x, cs[tok][0]);
                        cs[tok][1] = fmaf(wmat[1][k], xv.y, cs[tok][1]);
                        cs[tok][2] = fmaf(wmat[2][k], xv.z, cs[tok][2]);
                        cs[tok][3] = fmaf(wmat[3][k], xv.w, cs[tok][3]);
                    }
                }
            }
        }
        float4 wg = *(const float4*)(w20 + d);
#pragma unroll
        for (int tok = 0; tok < 4; tok++)
            part[tok][16] += cs[tok][0]*wg.x + cs[tok][1]*wg.y + cs[tok][2]*wg.z + cs[tok][3]*wg.w;
#pragma unroll
        for (int n = 0; n < 16; n++) {
            float4 wv = *(const float4*)(dt_w + n * D_INNER + d);
#pragma unroll
            for (int tok = 0; tok < 4; tok++)
                part[tok][n] = fmaf(cs[tok][0], wv.x, fmaf(cs[tok][1], wv.y,
                               fmaf(cs[tok][2], wv.z, fmaf(cs[tok][3], wv.w, part[tok][n]))));
        }
    }

    __shared__ float red[8][68];
#pragma unroll
    for (int tok = 0; tok < 4; tok++) {
#pragma unroll
        for (int r = 0; r < 17; r++) {
            float v = part[tok][r];
#pragma unroll
            for (int o = 16; o > 0; o >>= 1) v += __shfl_down_sync(0xffffffffu, v, o);
            if (lane == 0) red[wid][tok * 17 + r] = v;
        }
    }
    __syncthreads();
    if (tid < 68) {
        const int tok = tid / 17, r = tid - tok * 17;
        float s = 0.f;
#pragma unroll
        for (int w = 0; w < 8; w++) s += red[w][tid];
        if (r < 16) {
            const float delta = sp_(s + dt_b[r]);
            const float spA   = sp_(Avec[r]);
            g_dA[(m0 + tok) * D_ST + r] = expf(-delta * spA);
        } else {
            const float gamma = s + xproj_b[20];
            g_gs[m0 + tok] = gamma / (1.f + expf(-gamma));
        }
    }
}

// ---------------------------------------------------------------------------
// Per-chunk products of dA
// ---------------------------------------------------------------------------
__global__ void aprod_kernel()
{
    const int bc = blockIdx.x;
    const int n = threadIdx.x;
    const int b = bc / NCHUNK, c = bc % NCHUNK;
    float p = 1.f;
    const int base = (b * S_LEN + c * LCHUNK) * D_ST + n;
    for (int i = 0; i < LCHUNK; i++) p *= g_dA[base + i * D_ST];
    g_Ap[bc * D_ST + n] = p;
}

// ---------------------------------------------------------------------------
// Scan pass 1 (local, zero-init) with smem-staged dA
// ---------------------------------------------------------------------------
__global__ __launch_bounds__(256)
void scan_pass1(const float* __restrict__ Bm)
{
    __shared__ float s_a[LCHUNK * D_ST];    // 8 KB
    const int gid = blockIdx.x;
    const int d = ((gid & 7) << 8) + threadIdx.x;
    const int c = (gid >> 3) & (NCHUNK - 1);
    const int b = gid >> 7;
    const int m0 = b * S_LEN + c * LCHUNK;

    for (int i = threadIdx.x; i < LCHUNK * D_ST; i += 256) s_a[i] = g_dA[m0 * D_ST + i];
    __syncthreads();

    float dB[16];
#pragma unroll
    for (int q = 0; q < 4; q++) {
        float4 v = *(const float4*)(Bm + d * D_ST + 4 * q);
        dB[4*q+0] = sp_(v.x); dB[4*q+1] = sp_(v.y); dB[4*q+2] = sp_(v.z); dB[4*q+3] = sp_(v.w);
    }
    float h[16];
#pragma unroll
    for (int n = 0; n < 16; n++) h[n] = 0.f;

    const float* xp = g_xr + (size_t)m0 * 4096 + d;
    for (int i = 0; i < LCHUNK; i++) {
        const float u = __ldg(xp + (size_t)i * 4096);
#pragma unroll
        for (int q = 0; q < 4; q++) {
            float4 a4 = *(const float4*)(s_a + i * D_ST + 4 * q);
            h[4*q+0] = fmaf(h[4*q+0], a4.x, u * dB[4*q+0]);
            h[4*q+1] = fmaf(h[4*q+1], a4.y, u * dB[4*q+1]);
            h[4*q+2] = fmaf(h[4*q+2], a4.z, u * dB[4*q+2]);
            h[4*q+3] = fmaf(h[4*q+3], a4.w, u * dB[4*q+3]);
        }
    }
    const size_t o = ((size_t)(b * NCHUNK + c) * D_INNER + d) * D_ST;
#pragma unroll
    for (int q = 0; q < 4; q++)
        *(float4*)(g_hend + o + 4 * q) = make_float4(h[4*q], h[4*q+1], h[4*q+2], h[4*q+3]);
}

// ---------------------------------------------------------------------------
// Inter-chunk carry
// ---------------------------------------------------------------------------
__global__ void scan_carry()
{
    const int lin = blockIdx.x * 256 + threadIdx.x;
    const int n = lin & 15;
    const int d = (lin >> 4) & (D_INNER - 1);
    const int b = lin >> 15;
    float h = 0.f;
    for (int c = 0; c < NCHUNK; c++) {
        const size_t idx = ((size_t)(b * NCHUNK + c) * D_INNER + d) * D_ST + n;
        g_hin[idx] = h;
        h = h * g_Ap[(b * NCHUNK + c) * D_ST + n] + g_hend[idx];
    }
}

// ---------------------------------------------------------------------------
// Scan pass 2 -> g_y = tf32(y*silu(gamma)+res), with smem-staged dA & gs
// ---------------------------------------------------------------------------
__global__ __launch_bounds__(256)
void scan_pass2(const float* __restrict__ Bm, const float* __restrict__ Cm)
{
    __shared__ float s_a[LCHUNK * D_ST];
    __shared__ float s_g[LCHUNK];
    const int gid = blockIdx.x;
    const int d = ((gid & 7) << 8) + threadIdx.x;
    const int c = (gid >> 3) & (NCHUNK - 1);
    const int b = gid >> 7;
    const int m0 = b * S_LEN + c * LCHUNK;

    for (int i = threadIdx.x; i < LCHUNK * D_ST; i += 256) s_a[i] = g_dA[m0 * D_ST + i];
    for (int i = threadIdx.x; i < LCHUNK; i += 256) s_g[i] = g_gs[m0 + i];
    __syncthreads();

    float dB[16], dC[16];
#pragma unroll
    for (int q = 0; q < 4; q++) {
        float4 v = *(const float4*)(Bm + d * D_ST + 4 * q);
        dB[4*q+0] = sp_(v.x); dB[4*q+1] = sp_(v.y); dB[4*q+2] = sp_(v.z); dB[4*q+3] = sp_(v.w);
        float4 w = *(const float4*)(Cm + d * D_ST + 4 * q);
        dC[4*q+0] = w.x; dC[4*q+1] = w.y; dC[4*q+2] = w.z; dC[4*q+3] = w.w;
    }
    const size_t o = ((size_t)(b * NCHUNK + c) * D_INNER + d) * D_ST;
    float h[16];
#pragma unroll
    for (int q = 0; q < 4; q++) {
        float4 v = *(const float4*)(g_hin + o + 4 * q);
        h[4*q+0] = v.x; h[4*q+1] = v.y; h[4*q+2] = v.z; h[4*q+3] = v.w;
    }

    const float* xp = g_xr + (size_t)m0 * 4096 + d;
    const float* rp = g_xr + (size_t)m0 * 4096 + D_INNER + d;
    float* yp = g_y + (size_t)m0 * D_INNER + d;

    for (int i = 0; i < LCHUNK; i++) {
        const float u = __ldg(xp + (size_t)i * 4096);
        float y = 0.f;
#pragma unroll
        for (int q = 0; q < 4; q++) {
            float4 a4 = *(const float4*)(s_a + i * D_ST + 4 * q);
            h[4*q+0] = fmaf(h[4*q+0], a4.x, u * dB[4*q+0]);
            h[4*q+1] = fmaf(h[4*q+1], a4.y, u * dB[4*q+1]);
            h[4*q+2] = fmaf(h[4*q+2], a4.z, u * dB[4*q+2]);
            h[4*q+3] = fmaf(h[4*q+3], a4.w, u * dB[4*q+3]);
            y = fmaf(h[4*q+0], dC[4*q+0], y);
            y = fmaf(h[4*q+1], dC[4*q+1], y);
            y = fmaf(h[4*q+2], dC[4*q+2], y);
            y = fmaf(h[4*q+3], dC[4*q+3], y);
        }
        yp[(size_t)i * D_INNER] = tf32r(fmaf(y, s_g[i], __ldg(rp + (size_t)i * 4096)));
    }
}

// ---------------------------------------------------------------------------
// Launch
// ---------------------------------------------------------------------------
extern "C" void kernel_launch(void* const* d_in, const int* in_sizes, int n_in,
                              void* d_out, int out_size)
{
    const float* x       = (const float*)d_in[0];
    const float* in_w    = (const float*)d_in[1];
    const float* in_b    = (const float*)d_in[2];
    const float* conv_w  = (const float*)d_in[3];
    const float* conv_b  = (const float*)d_in[4];
    const float* xproj_w = (const float*)d_in[5];
    const float* xproj_b = (const float*)d_in[6];
    const float* dt_w    = (const float*)d_in[7];
    const float* dt_b    = (const float*)d_in[8];
    const float* A       = (const float*)d_in[9];
    const float* Bm      = (const float*)d_in[10];
    const float* Cm      = (const float*)d_in[11];
    const float* out_w   = (const float*)d_in[12];
    const float* out_b   = (const float*)d_in[13];
    float* out = (float*)d_out;

    float *xr, *y, *xt, *w1t, *w2t;
    cudaGetSymbolAddress((void**)&xr,  g_xr);
    cudaGetSymbolAddress((void**)&y,   g_y);
    cudaGetSymbolAddress((void**)&xt,  g_xt);
    cudaGetSymbolAddress((void**)&w1t, g_w1t);
    cudaGetSymbolAddress((void**)&w2t, g_w2t);

    cudaFuncSetAttribute(gemm_mma<1024, 4096>, cudaFuncAttributeMaxDynamicSharedMemorySize, GSMEM_BYTES);
    cudaFuncSetAttribute(gemm_mma<2048, 1024>, cudaFuncAttributeMaxDynamicSharedMemorySize, GSMEM_BYTES);

    // round inputs to tf32 (rna)
    k_tf32round<<<1024, 256>>>((const float4*)x,     (float4*)xt,  (M_ROWS * DIM_) / 4);
    k_tf32round<<<1024, 256>>>((const float4*)in_w,  (float4*)w1t, (4096 * DIM_) / 4);
    k_tf32round<<<1024, 256>>>((const float4*)out_w, (float4*)w2t, (DIM_ * D_INNER) / 4);

    // GEMM1: g_xr = x @ in_w^T + in_b     [8192, 4096]
    gemm_mma<1024, 4096><<<dim3(4096 / 128, M_ROWS / 256), 256, GSMEM_BYTES>>>(xt, w1t, in_b, xr);

    // conv + projections -> dA, silu(gamma)   (4 tokens per block)
    conv_proj<<<M_ROWS / 4, 256>>>(conv_w, conv_b, xproj_w, xproj_b, dt_w, dt_b, A);

    // chunked scan
    aprod_kernel<<<BATCH * NCHUNK, D_ST>>>();
    scan_pass1<<<BATCH * NCHUNK * (D_INNER / 256), 256>>>(Bm);
    scan_carry<<<(BATCH * D_INNER * D_ST) / 256, 256>>>();
    scan_pass2<<<BATCH * NCHUNK * (D_INNER / 256), 256>>>(Bm, Cm);

    // GEMM2: out = g_y @ out_w^T + out_b  [8192, 1024]
    gemm_mma<2048, 1024><<<dim3(1024 / 128, M_ROWS / 256), 256, GSMEM_BYTES>>>(y, w2t, out_b, out);
}